// round 7
// baseline (speedup 1.0000x reference)
#include <cuda_runtime.h>
#include <math.h>
#include <stdint.h>

// Fixed shapes for this dataset
#define NTOK_MAX 8192

// Scratch (no cudaMalloc allowed)
__device__ float g_h[NTOK_MAX * 4096];        // 128 MB intermediate (post-GELU)
__device__ int   g_eidx_up[NTOK_MAX * 2];
__device__ float g_prob_up[NTOK_MAX * 2];
__device__ int   g_eidx_dn[NTOK_MAX * 2];
__device__ float g_prob_dn[NTOK_MAX * 2];

// Truncation split fp32 -> (hi, lo) tf32 pair (raw fp32-layout bits for mma).
__device__ __forceinline__ void sp(float v, uint32_t& h, uint32_t& l) {
    uint32_t hb = __float_as_uint(v) & 0xFFFFE000u;
    h = hb;
    l = __float_as_uint(v - __uint_as_float(hb));
}

#define MMA_TF32(C, a0, a1, a2, a3, b0, b1)                                    \
    asm volatile(                                                              \
        "mma.sync.aligned.m16n8k8.row.col.f32.tf32.tf32.f32 "                  \
        "{%0,%1,%2,%3},{%4,%5,%6,%7},{%8,%9},{%0,%1,%2,%3};"                   \
        : "+f"((C)[0]), "+f"((C)[1]), "+f"((C)[2]), "+f"((C)[3])               \
        : "r"(a0), "r"(a1), "r"(a2), "r"(a3), "r"(b0), "r"(b1));

// 3xTF32: hi*hi + hi*lo + lo*hi  (lo*lo negligible)
#define MMA3(C, ah0, ah1, ah2, ah3, al0, al1, al2, al3, bh0, bh1, bl0, bl1)    \
    MMA_TF32(C, ah0, ah1, ah2, ah3, bh0, bh1);                                 \
    MMA_TF32(C, ah0, ah1, ah2, ah3, bl0, bl1);                                 \
    MMA_TF32(C, al0, al1, al2, al3, bh0, bh1);

// load+split an A-fragment from row-major tile (stride ≡ 4 mod 32: conflict-free)
#define LDFRAG_A(S, STRIDE, aoff)                                              \
    uint32_t ah0, ah1, ah2, ah3, al0, al1, al2, al3;                           \
    sp((S)[(aoff)],                    ah0, al0);                              \
    sp((S)[(aoff) + 8 * (STRIDE)],     ah1, al1);                              \
    sp((S)[(aoff) + 4],                ah2, al2);                              \
    sp((S)[(aoff) + 8 * (STRIDE) + 4], ah3, al3);

#define LDFRAG_B(S, boff)                                                      \
    uint32_t bh0, bh1, bl0, bl1;                                               \
    sp((S)[(boff)],     bh0, bl0);                                             \
    sp((S)[(boff) + 4], bh1, bl1);

// ---------------------------------------------------------------------------
// Router: logits = X[N,K] @ W[E,K]^T via 3xTF32 mma, then top-2 + softmax(2).
// Block = 64 tokens x 64 experts. 256 threads = 8 warps.
// Register-prefetch double buffering: LDG tile i+1 issued before compute of i.
// ---------------------------------------------------------------------------
__global__ void router_mma(const float* __restrict__ X,
                           const float* __restrict__ W,
                           int K, int phase)
{
    __shared__ float Xs[64 * 36];
    __shared__ float Ws[64 * 36];
    __shared__ float Ls[64 * 65];

    const int tid  = threadIdx.x;
    const int w    = tid >> 5;
    const int lane = tid & 31;
    const int grp  = lane >> 2;
    const int qc   = lane & 3;
    const int tok0 = blockIdx.x * 64;
    const int mtile = w >> 1;
    const int nbase = (w & 1) * 4;

    // staging coords for this thread (2 chunks of 256 float4s)
    const int r0 = tid >> 3,            c0 = (tid & 7) * 4;
    const int r1 = (tid + 256) >> 3,    c1 = ((tid + 256) & 7) * 4;

    float c[4][4];
#pragma unroll
    for (int t = 0; t < 4; t++)
#pragma unroll
        for (int q = 0; q < 4; q++) c[t][q] = 0.f;

    const int nT = K >> 5;
    float4 xv0, xv1, wv0, wv1;
    // prefetch tile 0
    xv0 = *(const float4*)&X[(size_t)(tok0 + r0) * K + c0];
    xv1 = *(const float4*)&X[(size_t)(tok0 + r1) * K + c1];
    wv0 = *(const float4*)&W[(size_t)r0 * K + c0];
    wv1 = *(const float4*)&W[(size_t)r1 * K + c1];

    for (int ti = 0; ti < nT; ti++) {
        // store staged tile
        *(float4*)&Xs[r0 * 36 + c0] = xv0;
        *(float4*)&Xs[r1 * 36 + c1] = xv1;
        *(float4*)&Ws[r0 * 36 + c0] = wv0;
        *(float4*)&Ws[r1 * 36 + c1] = wv1;
        __syncthreads();

        // prefetch next tile (overlaps compute below)
        if (ti + 1 < nT) {
            int kt = (ti + 1) * 32;
            xv0 = *(const float4*)&X[(size_t)(tok0 + r0) * K + kt + c0];
            xv1 = *(const float4*)&X[(size_t)(tok0 + r1) * K + kt + c1];
            wv0 = *(const float4*)&W[(size_t)r0 * K + kt + c0];
            wv1 = *(const float4*)&W[(size_t)r1 * K + kt + c1];
        }

#pragma unroll
        for (int kk = 0; kk < 4; kk++) {
            int k0 = kk * 8;
            int aoff = (mtile * 16 + grp) * 36 + k0 + qc;
            LDFRAG_A(Xs, 36, aoff);
#pragma unroll
            for (int t = 0; t < 4; t++) {
                int boff = ((nbase + t) * 8 + grp) * 36 + k0 + qc;
                LDFRAG_B(Ws, boff);
                MMA3(c[t], ah0, ah1, ah2, ah3, al0, al1, al2, al3, bh0, bh1, bl0, bl1);
            }
        }
        __syncthreads();
    }

    {
        int row0 = mtile * 16 + grp;
#pragma unroll
        for (int t = 0; t < 4; t++) {
            int col0 = (nbase + t) * 8 + 2 * qc;
            Ls[row0 * 65 + col0]           = c[t][0];
            Ls[row0 * 65 + col0 + 1]       = c[t][1];
            Ls[(row0 + 8) * 65 + col0]     = c[t][2];
            Ls[(row0 + 8) * 65 + col0 + 1] = c[t][3];
        }
    }
    __syncthreads();

    if (tid < 64) {
        const float* lrow = &Ls[tid * 65];
        float v0 = -1e30f; int i0 = 0;
#pragma unroll
        for (int e = 0; e < 64; e++) {
            float v = lrow[e];
            if (v > v0) { v0 = v; i0 = e; }
        }
        float v1 = -1e30f; int i1 = 0;
#pragma unroll
        for (int e = 0; e < 64; e++) {
            if (e == i0) continue;
            float v = lrow[e];
            if (v > v1) { v1 = v; i1 = e; }
        }
        float p0 = 1.0f / (1.0f + expf(v1 - v0));
        float p1 = 1.0f - p0;
        int n = tok0 + tid;
        int*   ei = phase ? g_eidx_dn : g_eidx_up;
        float* pr = phase ? g_prob_dn : g_prob_up;
        ei[n * 2 + 0] = i0;
        ei[n * 2 + 1] = i1;
        pr[n * 2 + 0] = p0;
        pr[n * 2 + 1] = p1;
    }
}

// ---------------------------------------------------------------------------
// Up layer (per token): Y = sum_k p_k * (A_e @ X @ B_e^T), X as 32x32 [i][j].
// Xs stride 40 (≡8 mod 32): col-major B-operand reads are conflict-free.
// smem: Xs 32x40 + As/Bs/Ts 64x36 = 32.8 KB.  256 threads = 8 warps.
// ---------------------------------------------------------------------------
__global__ void up_mma(const float* __restrict__ X,
                       const float* __restrict__ A,
                       const float* __restrict__ Bm,
                       const float* __restrict__ scale,
                       const float* __restrict__ bias)
{
    __shared__ float Xs[32 * 40];   // [i][j] row-major, stride 40
    __shared__ float As[64 * 36];   // A[o][i]
    __shared__ float Bs[64 * 36];   // B[p][j]
    __shared__ float Ts[64 * 36];   // T[o][j] (prob-scaled, fp32)

    const int tid  = threadIdx.x;
    const int w    = tid >> 5;
    const int lane = tid & 31;
    const int grp  = lane >> 2;
    const int qc   = lane & 3;
    const int n    = blockIdx.x;
    const int mtile = w >> 1;
    const int nbase = (w & 1) * 4;

    // load X row as 32x32 [i][j], coalesced float4
    {
        int i = tid >> 3, j4 = tid & 7;
        *(float4*)&Xs[i * 40 + j4 * 4] =
            *(const float4*)&X[(size_t)n * 1024 + i * 32 + j4 * 4];
    }

    const float sc = scale[0];
    const int   e0 = g_eidx_up[n * 2],  e1 = g_eidx_up[n * 2 + 1];
    const float p0 = g_prob_up[n * 2],  p1 = g_prob_up[n * 2 + 1];

    float c[4][4];
#pragma unroll
    for (int t = 0; t < 4; t++)
#pragma unroll
        for (int q = 0; q < 4; q++) c[t][q] = 0.f;

#pragma unroll 1
    for (int kk2 = 0; kk2 < 2; kk2++) {
        const int   e = kk2 ? e1 : e0;
        const float p = kk2 ? p1 : p0;
        const float* Ag = A  + (size_t)e * 2048;
        const float* Bg = Bm + (size_t)e * 2048;
        __syncthreads();
#pragma unroll
        for (int i = 0; i < 2; i++) {
            int idx4 = tid + i * 256;           // 0..511 (2048 floats)
            int row = idx4 >> 3, c4 = idx4 & 7;
            *(float4*)&As[row * 36 + c4 * 4] = *(const float4*)&Ag[idx4 * 4];
            *(float4*)&Bs[row * 36 + c4 * 4] = *(const float4*)&Bg[idx4 * 4];
        }
        __syncthreads();

        // GEMM1: T = A @ X ; warp: mtile rows, n-tiles (w&1)*2 + {0,1}
        float t1[2][4];
#pragma unroll
        for (int t = 0; t < 2; t++)
#pragma unroll
            for (int q = 0; q < 4; q++) t1[t][q] = 0.f;
#pragma unroll
        for (int kk = 0; kk < 4; kk++) {
            int k0 = kk * 8;
            int aoff = (mtile * 16 + grp) * 36 + k0 + qc;
            LDFRAG_A(As, 36, aoff);
#pragma unroll
            for (int t = 0; t < 2; t++) {
                // B-op = X col-major (k=i, n=j): addr (k0+qc)*40 + n0+grp
                int boff = (k0 + qc) * 40 + ((w & 1) * 2 + t) * 8 + grp;
                uint32_t bh0, bh1, bl0, bl1;
                sp(Xs[boff],          bh0, bl0);
                sp(Xs[boff + 4 * 40], bh1, bl1);
                MMA3(t1[t], ah0, ah1, ah2, ah3, al0, al1, al2, al3, bh0, bh1, bl0, bl1);
            }
        }
        {
            int row0 = mtile * 16 + grp;
#pragma unroll
            for (int t = 0; t < 2; t++) {
                int col0 = ((w & 1) * 2 + t) * 8 + 2 * qc;
                *(float2*)&Ts[row0 * 36 + col0]       = make_float2(p * t1[t][0], p * t1[t][1]);
                *(float2*)&Ts[(row0 + 8) * 36 + col0] = make_float2(p * t1[t][2], p * t1[t][3]);
            }
        }
        __syncthreads();

        // GEMM2: Y += T @ B^T
#pragma unroll
        for (int kk = 0; kk < 4; kk++) {
            int k0 = kk * 8;
            int aoff = (mtile * 16 + grp) * 36 + k0 + qc;
            LDFRAG_A(Ts, 36, aoff);
#pragma unroll
            for (int t = 0; t < 4; t++) {
                int boff = ((nbase + t) * 8 + grp) * 36 + k0 + qc;
                LDFRAG_B(Bs, boff);
                MMA3(c[t], ah0, ah1, ah2, ah3, al0, al1, al2, al3, bh0, bh1, bl0, bl1);
            }
        }
    }

    // epilogue: scale + bias + exact erf GELU
    float* Hrow = g_h + (size_t)n * 4096;
    const int row0 = mtile * 16 + grp;
#pragma unroll
    for (int t = 0; t < 4; t++) {
        int col0 = (nbase + t) * 8 + 2 * qc;
#pragma unroll
        for (int half = 0; half < 2; half++) {
            int row = row0 + half * 8;
            int oi = row * 64 + col0;
            float2 bv = *(const float2*)&bias[oi];
            float y0 = c[t][half * 2 + 0] * sc + bv.x;
            float y1 = c[t][half * 2 + 1] * sc + bv.y;
            float g0 = 0.5f * y0 * (1.0f + erff(y0 * 0.70710678118654752f));
            float g1 = 0.5f * y1 * (1.0f + erff(y1 * 0.70710678118654752f));
            *(float2*)(Hrow + oi) = make_float2(g0, g1);
        }
    }
}

// ---------------------------------------------------------------------------
// Down layer (per token): Y = sum_k p_k * (A_e @ H @ B_e^T), H as 64x64 [i][j].
// Hs stride 72 (≡8 mod 32): col-major B-operand reads are conflict-free.
// smem: Hs 64x72 + As/Bs/Ts 32x68 = 43.5 KB.
// ---------------------------------------------------------------------------
__global__ void down_mma(const float* __restrict__ A,
                         const float* __restrict__ Bm,
                         const float* __restrict__ scale,
                         const float* __restrict__ bias,
                         float* __restrict__ out)
{
    __shared__ float Hs[64 * 72];   // [i][j] row-major, stride 72
    __shared__ float As[32 * 68];   // A[o][i]
    __shared__ float Bs[32 * 68];   // B[p][j]
    __shared__ float Ts[32 * 68];   // T[o][j] (prob-scaled, fp32)

    const int tid  = threadIdx.x;
    const int w    = tid >> 5;
    const int lane = tid & 31;
    const int grp  = lane >> 2;
    const int qc   = lane & 3;
    const int n    = blockIdx.x;
    const int mtile  = w & 1;
    const int ntile2 = w >> 1;

    // load H row as 64x64 [i][j], coalesced float4
    const float* Xrow = g_h + (size_t)n * 4096;
#pragma unroll
    for (int i = 0; i < 4; i++) {
        int idx4 = tid + i * 256;               // 0..1023
        int r = idx4 >> 4, j4 = idx4 & 15;
        *(float4*)&Hs[r * 72 + j4 * 4] = *(const float4*)&Xrow[idx4 * 4];
    }

    const float sc = scale[0];
    const int   e0 = g_eidx_dn[n * 2],  e1 = g_eidx_dn[n * 2 + 1];
    const float p0 = g_prob_dn[n * 2],  p1 = g_prob_dn[n * 2 + 1];

    float c[4];
    c[0] = c[1] = c[2] = c[3] = 0.f;

#pragma unroll 1
    for (int kk2 = 0; kk2 < 2; kk2++) {
        const int   e = kk2 ? e1 : e0;
        const float p = kk2 ? p1 : p0;
        const float* Ag = A  + (size_t)e * 2048;
        const float* Bg = Bm + (size_t)e * 2048;
        __syncthreads();
#pragma unroll
        for (int i = 0; i < 2; i++) {
            int idx4 = tid + i * 256;           // 0..511 (2048 floats, 32x64)
            int row = idx4 >> 4, c4 = idx4 & 15;
            *(float4*)&As[row * 68 + c4 * 4] = *(const float4*)&Ag[idx4 * 4];
            *(float4*)&Bs[row * 68 + c4 * 4] = *(const float4*)&Bg[idx4 * 4];
        }
        __syncthreads();

        // GEMM1: T = A @ H ; warp: mtile rows, n-tiles ntile2*2 + {0,1}
        float t1[2][4];
#pragma unroll
        for (int t = 0; t < 2; t++)
#pragma unroll
            for (int q = 0; q < 4; q++) t1[t][q] = 0.f;
#pragma unroll
        for (int kk = 0; kk < 8; kk++) {
            int k0 = kk * 8;
            int aoff = (mtile * 16 + grp) * 68 + k0 + qc;
            LDFRAG_A(As, 68, aoff);
#pragma unroll
            for (int t = 0; t < 2; t++) {
                // B-op = H col-major (k=i, n=j): addr (k0+qc)*72 + n0+grp
                int boff = (k0 + qc) * 72 + (ntile2 * 2 + t) * 8 + grp;
                uint32_t bh0, bh1, bl0, bl1;
                sp(Hs[boff],          bh0, bl0);
                sp(Hs[boff + 4 * 72], bh1, bl1);
                MMA3(t1[t], ah0, ah1, ah2, ah3, al0, al1, al2, al3, bh0, bh1, bl0, bl1);
            }
        }
        {
            int row0 = mtile * 16 + grp;
#pragma unroll
            for (int t = 0; t < 2; t++) {
                int col0 = (ntile2 * 2 + t) * 8 + 2 * qc;
                *(float2*)&Ts[row0 * 68 + col0]       = make_float2(p * t1[t][0], p * t1[t][1]);
                *(float2*)&Ts[(row0 + 8) * 68 + col0] = make_float2(p * t1[t][2], p * t1[t][3]);
            }
        }
        __syncthreads();

        // GEMM2: Y += T @ B^T
#pragma unroll
        for (int kk = 0; kk < 8; kk++) {
            int k0 = kk * 8;
            int aoff = (mtile * 16 + grp) * 68 + k0 + qc;
            LDFRAG_A(Ts, 68, aoff);
            int boff = (ntile2 * 8 + grp) * 68 + k0 + qc;
            LDFRAG_B(Bs, boff);
            MMA3(c, ah0, ah1, ah2, ah3, al0, al1, al2, al3, bh0, bh1, bl0, bl1);
        }
    }

    float* orow = out + (size_t)n * 1024;
    const int row0 = mtile * 16 + grp;
    const int col0 = ntile2 * 8 + 2 * qc;
#pragma unroll
    for (int half = 0; half < 2; half++) {
        int row = row0 + half * 8;
        int oi = row * 32 + col0;
        float2 bv = *(const float2*)&bias[oi];
        float y0 = c[half * 2 + 0] * sc + bv.x;
        float y1 = c[half * 2 + 1] * sc + bv.y;
        *(float2*)(orow + oi) = make_float2(y0, y1);
    }
}

// ---------------------------------------------------------------------------
extern "C" void kernel_launch(void* const* d_in, const int* in_sizes, int n_in,
                              void* d_out, int out_size)
{
    const float* x        = (const float*)d_in[0];
    const float* W_up     = (const float*)d_in[1];
    const float* A_up     = (const float*)d_in[2];
    const float* B_up     = (const float*)d_in[3];
    const float* scale_up = (const float*)d_in[4];
    const float* bias_up  = (const float*)d_in[5];
    const float* W_dn     = (const float*)d_in[6];
    const float* A_dn     = (const float*)d_in[7];
    const float* B_dn     = (const float*)d_in[8];
    const float* scale_dn = (const float*)d_in[9];
    const float* bias_dn  = (const float*)d_in[10];
    float* out = (float*)d_out;

    const int N = in_sizes[0] / 1024;   // 8192 tokens

    float* hptr = nullptr;
    cudaGetSymbolAddress((void**)&hptr, g_h);

    router_mma<<<N / 64, 256>>>(x, W_up, 1024, 0);
    up_mma<<<N, 256>>>(x, A_up, B_up, scale_up, bias_up);
    router_mma<<<N / 64, 256>>>(hptr, W_dn, 4096, 1);
    down_mma<<<N, 256>>>(A_dn, B_dn, scale_dn, bias_dn, out);
}

// round 8
// speedup vs baseline: 1.4666x; 1.4666x over previous
#include <cuda_runtime.h>
#include <math.h>
#include <stdint.h>

// Fixed shapes for this dataset
#define NTOK_MAX 8192

// Scratch (no cudaMalloc allowed)
__device__ float g_h[NTOK_MAX * 4096];        // 128 MB intermediate (post-GELU)
__device__ int   g_eidx_up[NTOK_MAX * 2];
__device__ float g_prob_up[NTOK_MAX * 2];
__device__ int   g_eidx_dn[NTOK_MAX * 2];
__device__ float g_prob_dn[NTOK_MAX * 2];

// Truncation split fp32 -> (hi, lo) tf32 pair (raw fp32-layout bits for mma).
__device__ __forceinline__ void sp(float v, uint32_t& h, uint32_t& l) {
    uint32_t hb = __float_as_uint(v) & 0xFFFFE000u;
    h = hb;
    l = __float_as_uint(v - __uint_as_float(hb));
}

#define MMA_TF32(C, a0, a1, a2, a3, b0, b1)                                    \
    asm volatile(                                                              \
        "mma.sync.aligned.m16n8k8.row.col.f32.tf32.tf32.f32 "                  \
        "{%0,%1,%2,%3},{%4,%5,%6,%7},{%8,%9},{%0,%1,%2,%3};"                   \
        : "+f"((C)[0]), "+f"((C)[1]), "+f"((C)[2]), "+f"((C)[3])               \
        : "r"(a0), "r"(a1), "r"(a2), "r"(a3), "r"(b0), "r"(b1));

// 3xTF32: hi*hi + hi*lo + lo*hi  (lo*lo negligible)
#define MMA3(C, ah0, ah1, ah2, ah3, al0, al1, al2, al3, bh0, bh1, bl0, bl1)    \
    MMA_TF32(C, ah0, ah1, ah2, ah3, bh0, bh1);                                 \
    MMA_TF32(C, ah0, ah1, ah2, ah3, bl0, bl1);                                 \
    MMA_TF32(C, al0, al1, al2, al3, bh0, bh1);

// load+split an A-fragment from row-major tile (stride ≡ 4 mod 32: conflict-free)
#define LDFRAG_A(S, STRIDE, aoff)                                              \
    uint32_t ah0, ah1, ah2, ah3, al0, al1, al2, al3;                           \
    sp((S)[(aoff)],                    ah0, al0);                              \
    sp((S)[(aoff) + 8 * (STRIDE)],     ah1, al1);                              \
    sp((S)[(aoff) + 4],                ah2, al2);                              \
    sp((S)[(aoff) + 8 * (STRIDE) + 4], ah3, al3);

#define LDFRAG_B(S, boff)                                                      \
    uint32_t bh0, bh1, bl0, bl1;                                               \
    sp((S)[(boff)],     bh0, bl0);                                             \
    sp((S)[(boff) + 4], bh1, bl1);

// ---------------------------------------------------------------------------
// Router: logits = X[N,K] @ W[E,K]^T via 3xTF32 mma, then top-2 + softmax(2).
// Block = 64 tokens x 64 experts. 256 threads = 8 warps.
// Register-prefetch double buffering: LDG tile i+1 issued before compute of i.
// ---------------------------------------------------------------------------
__global__ void router_mma(const float* __restrict__ X,
                           const float* __restrict__ W,
                           int K, int phase)
{
    __shared__ float Xs[64 * 36];
    __shared__ float Ws[64 * 36];
    __shared__ float Ls[64 * 65];

    const int tid  = threadIdx.x;
    const int w    = tid >> 5;
    const int lane = tid & 31;
    const int grp  = lane >> 2;
    const int qc   = lane & 3;
    const int tok0 = blockIdx.x * 64;
    const int mtile = w >> 1;
    const int nbase = (w & 1) * 4;

    // staging coords for this thread (2 chunks of 256 float4s)
    const int r0 = tid >> 3,            c0 = (tid & 7) * 4;
    const int r1 = (tid + 256) >> 3,    c1 = ((tid + 256) & 7) * 4;

    float c[4][4];
#pragma unroll
    for (int t = 0; t < 4; t++)
#pragma unroll
        for (int q = 0; q < 4; q++) c[t][q] = 0.f;

    const int nT = K >> 5;
    float4 xv0, xv1, wv0, wv1;
    // prefetch tile 0
    xv0 = *(const float4*)&X[(size_t)(tok0 + r0) * K + c0];
    xv1 = *(const float4*)&X[(size_t)(tok0 + r1) * K + c1];
    wv0 = *(const float4*)&W[(size_t)r0 * K + c0];
    wv1 = *(const float4*)&W[(size_t)r1 * K + c1];

    for (int ti = 0; ti < nT; ti++) {
        // store staged tile
        *(float4*)&Xs[r0 * 36 + c0] = xv0;
        *(float4*)&Xs[r1 * 36 + c1] = xv1;
        *(float4*)&Ws[r0 * 36 + c0] = wv0;
        *(float4*)&Ws[r1 * 36 + c1] = wv1;
        __syncthreads();

        // prefetch next tile (overlaps compute below)
        if (ti + 1 < nT) {
            int kt = (ti + 1) * 32;
            xv0 = *(const float4*)&X[(size_t)(tok0 + r0) * K + kt + c0];
            xv1 = *(const float4*)&X[(size_t)(tok0 + r1) * K + kt + c1];
            wv0 = *(const float4*)&W[(size_t)r0 * K + kt + c0];
            wv1 = *(const float4*)&W[(size_t)r1 * K + kt + c1];
        }

#pragma unroll
        for (int kk = 0; kk < 4; kk++) {
            int k0 = kk * 8;
            int aoff = (mtile * 16 + grp) * 36 + k0 + qc;
            LDFRAG_A(Xs, 36, aoff);
#pragma unroll
            for (int t = 0; t < 4; t++) {
                int boff = ((nbase + t) * 8 + grp) * 36 + k0 + qc;
                LDFRAG_B(Ws, boff);
                MMA3(c[t], ah0, ah1, ah2, ah3, al0, al1, al2, al3, bh0, bh1, bl0, bl1);
            }
        }
        __syncthreads();
    }

    {
        int row0 = mtile * 16 + grp;
#pragma unroll
        for (int t = 0; t < 4; t++) {
            int col0 = (nbase + t) * 8 + 2 * qc;
            Ls[row0 * 65 + col0]           = c[t][0];
            Ls[row0 * 65 + col0 + 1]       = c[t][1];
            Ls[(row0 + 8) * 65 + col0]     = c[t][2];
            Ls[(row0 + 8) * 65 + col0 + 1] = c[t][3];
        }
    }
    __syncthreads();

    if (tid < 64) {
        const float* lrow = &Ls[tid * 65];
        float v0 = -1e30f; int i0 = 0;
#pragma unroll
        for (int e = 0; e < 64; e++) {
            float v = lrow[e];
            if (v > v0) { v0 = v; i0 = e; }
        }
        float v1 = -1e30f; int i1 = 0;
#pragma unroll
        for (int e = 0; e < 64; e++) {
            if (e == i0) continue;
            float v = lrow[e];
            if (v > v1) { v1 = v; i1 = e; }
        }
        float p0 = 1.0f / (1.0f + expf(v1 - v0));
        float p1 = 1.0f - p0;
        int n = tok0 + tid;
        int*   ei = phase ? g_eidx_dn : g_eidx_up;
        float* pr = phase ? g_prob_dn : g_prob_up;
        ei[n * 2 + 0] = i0;
        ei[n * 2 + 1] = i1;
        pr[n * 2 + 0] = p0;
        pr[n * 2 + 1] = p1;
    }
}

// ---------------------------------------------------------------------------
// Up layer (per token): Y = sum_k p_k * (A_e @ X @ B_e^T), X as 32x32 [i][j].
// Xs stride 40 (≡8 mod 32): col-major B-operand reads are conflict-free.
// smem: Xs 32x40 + As/Bs/Ts 64x36 = 32.8 KB.  256 threads = 8 warps.
// ---------------------------------------------------------------------------
__global__ void up_mma(const float* __restrict__ X,
                       const float* __restrict__ A,
                       const float* __restrict__ Bm,
                       const float* __restrict__ scale,
                       const float* __restrict__ bias)
{
    __shared__ float Xs[32 * 40];   // [i][j] row-major, stride 40
    __shared__ float As[64 * 36];   // A[o][i]
    __shared__ float Bs[64 * 36];   // B[p][j]
    __shared__ float Ts[64 * 36];   // T[o][j] (prob-scaled, fp32)

    const int tid  = threadIdx.x;
    const int w    = tid >> 5;
    const int lane = tid & 31;
    const int grp  = lane >> 2;
    const int qc   = lane & 3;
    const int n    = blockIdx.x;
    const int mtile = w >> 1;
    const int nbase = (w & 1) * 4;

    // load X row as 32x32 [i][j], coalesced float4
    {
        int i = tid >> 3, j4 = tid & 7;
        *(float4*)&Xs[i * 40 + j4 * 4] =
            *(const float4*)&X[(size_t)n * 1024 + i * 32 + j4 * 4];
    }

    const float sc = scale[0];
    const int   e0 = g_eidx_up[n * 2],  e1 = g_eidx_up[n * 2 + 1];
    const float p0 = g_prob_up[n * 2],  p1 = g_prob_up[n * 2 + 1];

    float c[4][4];
#pragma unroll
    for (int t = 0; t < 4; t++)
#pragma unroll
        for (int q = 0; q < 4; q++) c[t][q] = 0.f;

#pragma unroll 1
    for (int kk2 = 0; kk2 < 2; kk2++) {
        const int   e = kk2 ? e1 : e0;
        const float p = kk2 ? p1 : p0;
        const float* Ag = A  + (size_t)e * 2048;
        const float* Bg = Bm + (size_t)e * 2048;
        __syncthreads();
#pragma unroll
        for (int i = 0; i < 2; i++) {
            int idx4 = tid + i * 256;           // 0..511 (2048 floats)
            int row = idx4 >> 3, c4 = idx4 & 7;
            *(float4*)&As[row * 36 + c4 * 4] = *(const float4*)&Ag[idx4 * 4];
            *(float4*)&Bs[row * 36 + c4 * 4] = *(const float4*)&Bg[idx4 * 4];
        }
        __syncthreads();

        // GEMM1: T = A @ X ; warp: mtile rows, n-tiles (w&1)*2 + {0,1}
        float t1[2][4];
#pragma unroll
        for (int t = 0; t < 2; t++)
#pragma unroll
            for (int q = 0; q < 4; q++) t1[t][q] = 0.f;
#pragma unroll
        for (int kk = 0; kk < 4; kk++) {
            int k0 = kk * 8;
            int aoff = (mtile * 16 + grp) * 36 + k0 + qc;
            LDFRAG_A(As, 36, aoff);
#pragma unroll
            for (int t = 0; t < 2; t++) {
                // B-op = X col-major (k=i, n=j): addr (k0+qc)*40 + n0+grp
                int boff = (k0 + qc) * 40 + ((w & 1) * 2 + t) * 8 + grp;
                uint32_t bh0, bh1, bl0, bl1;
                sp(Xs[boff],          bh0, bl0);
                sp(Xs[boff + 4 * 40], bh1, bl1);
                MMA3(t1[t], ah0, ah1, ah2, ah3, al0, al1, al2, al3, bh0, bh1, bl0, bl1);
            }
        }
        {
            int row0 = mtile * 16 + grp;
#pragma unroll
            for (int t = 0; t < 2; t++) {
                int col0 = ((w & 1) * 2 + t) * 8 + 2 * qc;
                *(float2*)&Ts[row0 * 36 + col0]       = make_float2(p * t1[t][0], p * t1[t][1]);
                *(float2*)&Ts[(row0 + 8) * 36 + col0] = make_float2(p * t1[t][2], p * t1[t][3]);
            }
        }
        __syncthreads();

        // GEMM2: Y += T @ B^T
#pragma unroll
        for (int kk = 0; kk < 4; kk++) {
            int k0 = kk * 8;
            int aoff = (mtile * 16 + grp) * 36 + k0 + qc;
            LDFRAG_A(Ts, 36, aoff);
#pragma unroll
            for (int t = 0; t < 4; t++) {
                int boff = ((nbase + t) * 8 + grp) * 36 + k0 + qc;
                LDFRAG_B(Bs, boff);
                MMA3(c[t], ah0, ah1, ah2, ah3, al0, al1, al2, al3, bh0, bh1, bl0, bl1);
            }
        }
    }

    // epilogue: scale + bias + exact erf GELU
    float* Hrow = g_h + (size_t)n * 4096;
    const int row0 = mtile * 16 + grp;
#pragma unroll
    for (int t = 0; t < 4; t++) {
        int col0 = (nbase + t) * 8 + 2 * qc;
#pragma unroll
        for (int half = 0; half < 2; half++) {
            int row = row0 + half * 8;
            int oi = row * 64 + col0;
            float2 bv = *(const float2*)&bias[oi];
            float y0 = c[t][half * 2 + 0] * sc + bv.x;
            float y1 = c[t][half * 2 + 1] * sc + bv.y;
            float g0 = 0.5f * y0 * (1.0f + erff(y0 * 0.70710678118654752f));
            float g1 = 0.5f * y1 * (1.0f + erff(y1 * 0.70710678118654752f));
            *(float2*)(Hrow + oi) = make_float2(g0, g1);
        }
    }
}

// ---------------------------------------------------------------------------
// Down layer (per token): Y = sum_k p_k * (A_e @ H @ B_e^T), H as 64x64 [i][j].
// Hs stride 72 (≡8 mod 32): col-major B-operand reads are conflict-free.
// smem: Hs 64x72 + As/Bs/Ts 32x68 = 43.5 KB.
// ---------------------------------------------------------------------------
__global__ void down_mma(const float* __restrict__ A,
                         const float* __restrict__ Bm,
                         const float* __restrict__ scale,
                         const float* __restrict__ bias,
                         float* __restrict__ out)
{
    __shared__ float Hs[64 * 72];   // [i][j] row-major, stride 72
    __shared__ float As[32 * 68];   // A[o][i]
    __shared__ float Bs[32 * 68];   // B[p][j]
    __shared__ float Ts[32 * 68];   // T[o][j] (prob-scaled, fp32)

    const int tid  = threadIdx.x;
    const int w    = tid >> 5;
    const int lane = tid & 31;
    const int grp  = lane >> 2;
    const int qc   = lane & 3;
    const int n    = blockIdx.x;
    const int mtile  = w & 1;
    const int ntile2 = w >> 1;

    // load H row as 64x64 [i][j], coalesced float4
    const float* Xrow = g_h + (size_t)n * 4096;
#pragma unroll
    for (int i = 0; i < 4; i++) {
        int idx4 = tid + i * 256;               // 0..1023
        int r = idx4 >> 4, j4 = idx4 & 15;
        *(float4*)&Hs[r * 72 + j4 * 4] = *(const float4*)&Xrow[idx4 * 4];
    }

    const float sc = scale[0];
    const int   e0 = g_eidx_dn[n * 2],  e1 = g_eidx_dn[n * 2 + 1];
    const float p0 = g_prob_dn[n * 2],  p1 = g_prob_dn[n * 2 + 1];

    float c[4];
    c[0] = c[1] = c[2] = c[3] = 0.f;

#pragma unroll 1
    for (int kk2 = 0; kk2 < 2; kk2++) {
        const int   e = kk2 ? e1 : e0;
        const float p = kk2 ? p1 : p0;
        const float* Ag = A  + (size_t)e * 2048;
        const float* Bg = Bm + (size_t)e * 2048;
        __syncthreads();
#pragma unroll
        for (int i = 0; i < 2; i++) {
            int idx4 = tid + i * 256;           // 0..511 (2048 floats, 32x64)
            int row = idx4 >> 4, c4 = idx4 & 15;
            *(float4*)&As[row * 68 + c4 * 4] = *(const float4*)&Ag[idx4 * 4];
            *(float4*)&Bs[row * 68 + c4 * 4] = *(const float4*)&Bg[idx4 * 4];
        }
        __syncthreads();

        // GEMM1: T = A @ H ; warp: mtile rows, n-tiles ntile2*2 + {0,1}
        float t1[2][4];
#pragma unroll
        for (int t = 0; t < 2; t++)
#pragma unroll
            for (int q = 0; q < 4; q++) t1[t][q] = 0.f;
#pragma unroll
        for (int kk = 0; kk < 8; kk++) {
            int k0 = kk * 8;
            int aoff = (mtile * 16 + grp) * 68 + k0 + qc;
            LDFRAG_A(As, 68, aoff);
#pragma unroll
            for (int t = 0; t < 2; t++) {
                // B-op = H col-major (k=i, n=j): addr (k0+qc)*72 + n0+grp
                int boff = (k0 + qc) * 72 + (ntile2 * 2 + t) * 8 + grp;
                uint32_t bh0, bh1, bl0, bl1;
                sp(Hs[boff],          bh0, bl0);
                sp(Hs[boff + 4 * 72], bh1, bl1);
                MMA3(t1[t], ah0, ah1, ah2, ah3, al0, al1, al2, al3, bh0, bh1, bl0, bl1);
            }
        }
        {
            int row0 = mtile * 16 + grp;
#pragma unroll
            for (int t = 0; t < 2; t++) {
                int col0 = (ntile2 * 2 + t) * 8 + 2 * qc;
                *(float2*)&Ts[row0 * 68 + col0]       = make_float2(p * t1[t][0], p * t1[t][1]);
                *(float2*)&Ts[(row0 + 8) * 68 + col0] = make_float2(p * t1[t][2], p * t1[t][3]);
            }
        }
        __syncthreads();

        // GEMM2: Y += T @ B^T
#pragma unroll
        for (int kk = 0; kk < 8; kk++) {
            int k0 = kk * 8;
            int aoff = (mtile * 16 + grp) * 68 + k0 + qc;
            LDFRAG_A(Ts, 68, aoff);
            int boff = (ntile2 * 8 + grp) * 68 + k0 + qc;
            LDFRAG_B(Bs, boff);
            MMA3(c, ah0, ah1, ah2, ah3, al0, al1, al2, al3, bh0, bh1, bl0, bl1);
        }
    }

    float* orow = out + (size_t)n * 1024;
    const int row0 = mtile * 16 + grp;
    const int col0 = ntile2 * 8 + 2 * qc;
#pragma unroll
    for (int half = 0; half < 2; half++) {
        int row = row0 + half * 8;
        int oi = row * 32 + col0;
        float2 bv = *(const float2*)&bias[oi];
        float y0 = c[half * 2 + 0] * sc + bv.x;
        float y1 = c[half * 2 + 1] * sc + bv.y;
        *(float2*)(orow + oi) = make_float2(y0, y1);
    }
}

// ---------------------------------------------------------------------------
extern "C" void kernel_launch(void* const* d_in, const int* in_sizes, int n_in,
                              void* d_out, int out_size)
{
    const float* x        = (const float*)d_in[0];
    const float* W_up     = (const float*)d_in[1];
    const float* A_up     = (const float*)d_in[2];
    const float* B_up     = (const float*)d_in[3];
    const float* scale_up = (const float*)d_in[4];
    const float* bias_up  = (const float*)d_in[5];
    const float* W_dn     = (const float*)d_in[6];
    const float* A_dn     = (const float*)d_in[7];
    const float* B_dn     = (const float*)d_in[8];
    const float* scale_dn = (const float*)d_in[9];
    const float* bias_dn  = (const float*)d_in[10];
    float* out = (float*)d_out;

    const int N = in_sizes[0] / 1024;   // 8192 tokens

    float* hptr = nullptr;
    cudaGetSymbolAddress((void**)&hptr, g_h);

    router_mma<<<N / 64, 256>>>(x, W_up, 1024, 0);
    up_mma<<<N, 256>>>(x, A_up, B_up, scale_up, bias_up);
    router_mma<<<N / 64, 256>>>(hptr, W_dn, 4096, 1);
    down_mma<<<N, 256>>>(A_dn, B_dn, scale_dn, bias_dn, out);
}

// round 9
// speedup vs baseline: 1.4684x; 1.0012x over previous
#include <cuda_runtime.h>
#include <math.h>
#include <stdint.h>

// Fixed shapes for this dataset
#define NTOK_MAX 8192

// Scratch (no cudaMalloc allowed)
__device__ float g_h[NTOK_MAX * 4096];        // 128 MB intermediate (post-GELU)
__device__ int   g_eidx_up[NTOK_MAX * 2];
__device__ float g_prob_up[NTOK_MAX * 2];
__device__ int   g_eidx_dn[NTOK_MAX * 2];
__device__ float g_prob_dn[NTOK_MAX * 2];

// Truncation split fp32 -> (hi, lo) tf32 pair (raw fp32-layout bits for mma).
__device__ __forceinline__ void sp(float v, uint32_t& h, uint32_t& l) {
    uint32_t hb = __float_as_uint(v) & 0xFFFFE000u;
    h = hb;
    l = __float_as_uint(v - __uint_as_float(hb));
}

#define MMA_TF32(C, a0, a1, a2, a3, b0, b1)                                    \
    asm volatile(                                                              \
        "mma.sync.aligned.m16n8k8.row.col.f32.tf32.tf32.f32 "                  \
        "{%0,%1,%2,%3},{%4,%5,%6,%7},{%8,%9},{%0,%1,%2,%3};"                   \
        : "+f"((C)[0]), "+f"((C)[1]), "+f"((C)[2]), "+f"((C)[3])               \
        : "r"(a0), "r"(a1), "r"(a2), "r"(a3), "r"(b0), "r"(b1));

// 3xTF32: hi*hi + hi*lo + lo*hi  (lo*lo negligible)
#define MMA3(C, ah0, ah1, ah2, ah3, al0, al1, al2, al3, bh0, bh1, bl0, bl1)    \
    MMA_TF32(C, ah0, ah1, ah2, ah3, bh0, bh1);                                 \
    MMA_TF32(C, ah0, ah1, ah2, ah3, bl0, bl1);                                 \
    MMA_TF32(C, al0, al1, al2, al3, bh0, bh1);

// load+split an A-fragment from row-major tile (stride ≡ 4 mod 32: conflict-free)
#define LDFRAG_A(S, STRIDE, aoff)                                              \
    uint32_t ah0, ah1, ah2, ah3, al0, al1, al2, al3;                           \
    sp((S)[(aoff)],                    ah0, al0);                              \
    sp((S)[(aoff) + 8 * (STRIDE)],     ah1, al1);                              \
    sp((S)[(aoff) + 4],                ah2, al2);                              \
    sp((S)[(aoff) + 8 * (STRIDE) + 4], ah3, al3);

#define LDFRAG_B(S, boff)                                                      \
    uint32_t bh0, bh1, bl0, bl1;                                               \
    sp((S)[(boff)],     bh0, bl0);                                             \
    sp((S)[(boff) + 4], bh1, bl1);

// ---------------------------------------------------------------------------
// Router: logits = X[N,K] @ W[E,K]^T via 3xTF32 mma, then top-2 + softmax(2).
// Block = 64 tokens x 64 experts. 256 threads = 8 warps.
// Register-prefetch double buffering: LDG tile i+1 issued before compute of i.
// ---------------------------------------------------------------------------
__global__ void __launch_bounds__(256) router_mma(const float* __restrict__ X,
                                                  const float* __restrict__ W,
                                                  int K, int phase)
{
    __shared__ float Xs[64 * 36];
    __shared__ float Ws[64 * 36];
    __shared__ float Ls[64 * 65];

    const int tid  = threadIdx.x;
    const int w    = tid >> 5;
    const int lane = tid & 31;
    const int grp  = lane >> 2;
    const int qc   = lane & 3;
    const int tok0 = blockIdx.x * 64;
    const int mtile = w >> 1;
    const int nbase = (w & 1) * 4;

    // staging coords for this thread (2 chunks of 256 float4s)
    const int r0 = tid >> 3,            c0 = (tid & 7) * 4;
    const int r1 = (tid + 256) >> 3,    c1 = ((tid + 256) & 7) * 4;

    float c[4][4];
#pragma unroll
    for (int t = 0; t < 4; t++)
#pragma unroll
        for (int q = 0; q < 4; q++) c[t][q] = 0.f;

    const int nT = K >> 5;
    float4 xv0, xv1, wv0, wv1;
    // prefetch tile 0
    xv0 = *(const float4*)&X[(size_t)(tok0 + r0) * K + c0];
    xv1 = *(const float4*)&X[(size_t)(tok0 + r1) * K + c1];
    wv0 = *(const float4*)&W[(size_t)r0 * K + c0];
    wv1 = *(const float4*)&W[(size_t)r1 * K + c1];

    for (int ti = 0; ti < nT; ti++) {
        // store staged tile
        *(float4*)&Xs[r0 * 36 + c0] = xv0;
        *(float4*)&Xs[r1 * 36 + c1] = xv1;
        *(float4*)&Ws[r0 * 36 + c0] = wv0;
        *(float4*)&Ws[r1 * 36 + c1] = wv1;
        __syncthreads();

        // prefetch next tile (overlaps compute below)
        if (ti + 1 < nT) {
            int kt = (ti + 1) * 32;
            xv0 = *(const float4*)&X[(size_t)(tok0 + r0) * K + kt + c0];
            xv1 = *(const float4*)&X[(size_t)(tok0 + r1) * K + kt + c1];
            wv0 = *(const float4*)&W[(size_t)r0 * K + kt + c0];
            wv1 = *(const float4*)&W[(size_t)r1 * K + kt + c1];
        }

#pragma unroll
        for (int kk = 0; kk < 4; kk++) {
            int k0 = kk * 8;
            int aoff = (mtile * 16 + grp) * 36 + k0 + qc;
            LDFRAG_A(Xs, 36, aoff);
#pragma unroll
            for (int t = 0; t < 4; t++) {
                int boff = ((nbase + t) * 8 + grp) * 36 + k0 + qc;
                LDFRAG_B(Ws, boff);
                MMA3(c[t], ah0, ah1, ah2, ah3, al0, al1, al2, al3, bh0, bh1, bl0, bl1);
            }
        }
        __syncthreads();
    }

    {
        int row0 = mtile * 16 + grp;
#pragma unroll
        for (int t = 0; t < 4; t++) {
            int col0 = (nbase + t) * 8 + 2 * qc;
            Ls[row0 * 65 + col0]           = c[t][0];
            Ls[row0 * 65 + col0 + 1]       = c[t][1];
            Ls[(row0 + 8) * 65 + col0]     = c[t][2];
            Ls[(row0 + 8) * 65 + col0 + 1] = c[t][3];
        }
    }
    __syncthreads();

    if (tid < 64) {
        const float* lrow = &Ls[tid * 65];
        float v0 = -1e30f; int i0 = 0;
#pragma unroll
        for (int e = 0; e < 64; e++) {
            float v = lrow[e];
            if (v > v0) { v0 = v; i0 = e; }
        }
        float v1 = -1e30f; int i1 = 0;
#pragma unroll
        for (int e = 0; e < 64; e++) {
            if (e == i0) continue;
            float v = lrow[e];
            if (v > v1) { v1 = v; i1 = e; }
        }
        float p0 = 1.0f / (1.0f + expf(v1 - v0));
        float p1 = 1.0f - p0;
        int n = tok0 + tid;
        int*   ei = phase ? g_eidx_dn : g_eidx_up;
        float* pr = phase ? g_prob_dn : g_prob_up;
        ei[n * 2 + 0] = i0;
        ei[n * 2 + 1] = i1;
        pr[n * 2 + 0] = p0;
        pr[n * 2 + 1] = p1;
    }
}

// ---------------------------------------------------------------------------
// Up layer (per token): Y = sum_k p_k * (A_e @ X @ B_e^T), X as 32x32 [i][j].
// ATs buffer aliases As (GEMM1 A-operand) and Ts (GEMM2 A-operand) — their
// lifetimes are disjoint within one expert iteration (extra sync separates).
// smem: Xs 32x40 + ATs/Bs 64x36 = 23.6 KB -> 8 blocks/SM (warp-capped, 100%).
// ---------------------------------------------------------------------------
__global__ void __launch_bounds__(256) up_mma(const float* __restrict__ X,
                                              const float* __restrict__ A,
                                              const float* __restrict__ Bm,
                                              const float* __restrict__ scale,
                                              const float* __restrict__ bias)
{
    __shared__ float Xs[32 * 40];    // [i][j] row-major, stride 40
    __shared__ float ATs[64 * 36];   // As (GEMM1) then Ts (GEMM2)
    __shared__ float Bs[64 * 36];    // B[p][j]

    const int tid  = threadIdx.x;
    const int w    = tid >> 5;
    const int lane = tid & 31;
    const int grp  = lane >> 2;
    const int qc   = lane & 3;
    const int n    = blockIdx.x;
    const int mtile = w >> 1;
    const int nbase = (w & 1) * 4;

    // load X row as 32x32 [i][j], coalesced float4
    {
        int i = tid >> 3, j4 = tid & 7;
        *(float4*)&Xs[i * 40 + j4 * 4] =
            *(const float4*)&X[(size_t)n * 1024 + i * 32 + j4 * 4];
    }

    const float sc = scale[0];
    const int   e0 = g_eidx_up[n * 2],  e1 = g_eidx_up[n * 2 + 1];
    const float p0 = g_prob_up[n * 2],  p1 = g_prob_up[n * 2 + 1];

    float c[4][4];
#pragma unroll
    for (int t = 0; t < 4; t++)
#pragma unroll
        for (int q = 0; q < 4; q++) c[t][q] = 0.f;

#pragma unroll 1
    for (int kk2 = 0; kk2 < 2; kk2++) {
        const int   e = kk2 ? e1 : e0;
        const float p = kk2 ? p1 : p0;
        const float* Ag = A  + (size_t)e * 2048;
        const float* Bg = Bm + (size_t)e * 2048;
        __syncthreads();    // prev GEMM2 done reading ATs/Bs (and Xs store visible)
#pragma unroll
        for (int i = 0; i < 2; i++) {
            int idx4 = tid + i * 256;           // 0..511 (2048 floats)
            int row = idx4 >> 3, c4 = idx4 & 7;
            *(float4*)&ATs[row * 36 + c4 * 4] = *(const float4*)&Ag[idx4 * 4];
            *(float4*)&Bs[row * 36 + c4 * 4]  = *(const float4*)&Bg[idx4 * 4];
        }
        __syncthreads();

        // GEMM1: T = A @ X ; warp: mtile rows, n-tiles (w&1)*2 + {0,1}
        float t1[2][4];
#pragma unroll
        for (int t = 0; t < 2; t++)
#pragma unroll
            for (int q = 0; q < 4; q++) t1[t][q] = 0.f;
#pragma unroll
        for (int kk = 0; kk < 4; kk++) {
            int k0 = kk * 8;
            int aoff = (mtile * 16 + grp) * 36 + k0 + qc;
            LDFRAG_A(ATs, 36, aoff);
#pragma unroll
            for (int t = 0; t < 2; t++) {
                // B-op = X col-major (k=i, n=j): addr (k0+qc)*40 + n0+grp
                int boff = (k0 + qc) * 40 + ((w & 1) * 2 + t) * 8 + grp;
                uint32_t bh0, bh1, bl0, bl1;
                sp(Xs[boff],          bh0, bl0);
                sp(Xs[boff + 4 * 40], bh1, bl1);
                MMA3(t1[t], ah0, ah1, ah2, ah3, al0, al1, al2, al3, bh0, bh1, bl0, bl1);
            }
        }
        __syncthreads();    // all warps done reading As before Ts overwrites it
        {
            int row0 = mtile * 16 + grp;
#pragma unroll
            for (int t = 0; t < 2; t++) {
                int col0 = ((w & 1) * 2 + t) * 8 + 2 * qc;
                *(float2*)&ATs[row0 * 36 + col0]       = make_float2(p * t1[t][0], p * t1[t][1]);
                *(float2*)&ATs[(row0 + 8) * 36 + col0] = make_float2(p * t1[t][2], p * t1[t][3]);
            }
        }
        __syncthreads();

        // GEMM2: Y += T @ B^T
#pragma unroll
        for (int kk = 0; kk < 4; kk++) {
            int k0 = kk * 8;
            int aoff = (mtile * 16 + grp) * 36 + k0 + qc;
            LDFRAG_A(ATs, 36, aoff);
#pragma unroll
            for (int t = 0; t < 4; t++) {
                int boff = ((nbase + t) * 8 + grp) * 36 + k0 + qc;
                LDFRAG_B(Bs, boff);
                MMA3(c[t], ah0, ah1, ah2, ah3, al0, al1, al2, al3, bh0, bh1, bl0, bl1);
            }
        }
    }

    // epilogue: scale + bias + exact erf GELU
    float* Hrow = g_h + (size_t)n * 4096;
    const int row0 = mtile * 16 + grp;
#pragma unroll
    for (int t = 0; t < 4; t++) {
        int col0 = (nbase + t) * 8 + 2 * qc;
#pragma unroll
        for (int half = 0; half < 2; half++) {
            int row = row0 + half * 8;
            int oi = row * 64 + col0;
            float2 bv = *(const float2*)&bias[oi];
            float y0 = c[t][half * 2 + 0] * sc + bv.x;
            float y1 = c[t][half * 2 + 1] * sc + bv.y;
            float g0 = 0.5f * y0 * (1.0f + erff(y0 * 0.70710678118654752f));
            float g1 = 0.5f * y1 * (1.0f + erff(y1 * 0.70710678118654752f));
            *(float2*)(Hrow + oi) = make_float2(g0, g1);
        }
    }
}

// ---------------------------------------------------------------------------
// Down layer (per token): Y = sum_k p_k * (A_e @ H @ B_e^T), H as 64x64 [i][j].
// ATs aliases As (GEMM1) and Ts (GEMM2); extra sync separates lifetimes.
// smem: Hs 64x72 + ATs/Bs 32x68 = 36.6 KB -> 6 blocks/SM (48 warps, 75%).
// ---------------------------------------------------------------------------
__global__ void __launch_bounds__(256) down_mma(const float* __restrict__ A,
                                                const float* __restrict__ Bm,
                                                const float* __restrict__ scale,
                                                const float* __restrict__ bias,
                                                float* __restrict__ out)
{
    __shared__ float Hs[64 * 72];    // [i][j] row-major, stride 72
    __shared__ float ATs[32 * 68];   // As (GEMM1) then Ts (GEMM2)
    __shared__ float Bs[32 * 68];    // B[p][j]

    const int tid  = threadIdx.x;
    const int w    = tid >> 5;
    const int lane = tid & 31;
    const int grp  = lane >> 2;
    const int qc   = lane & 3;
    const int n    = blockIdx.x;
    const int mtile  = w & 1;
    const int ntile2 = w >> 1;

    // load H row as 64x64 [i][j], coalesced float4
    const float* Xrow = g_h + (size_t)n * 4096;
#pragma unroll
    for (int i = 0; i < 4; i++) {
        int idx4 = tid + i * 256;               // 0..1023
        int r = idx4 >> 4, j4 = idx4 & 15;
        *(float4*)&Hs[r * 72 + j4 * 4] = *(const float4*)&Xrow[idx4 * 4];
    }

    const float sc = scale[0];
    const int   e0 = g_eidx_dn[n * 2],  e1 = g_eidx_dn[n * 2 + 1];
    const float p0 = g_prob_dn[n * 2],  p1 = g_prob_dn[n * 2 + 1];

    float c[4];
    c[0] = c[1] = c[2] = c[3] = 0.f;

#pragma unroll 1
    for (int kk2 = 0; kk2 < 2; kk2++) {
        const int   e = kk2 ? e1 : e0;
        const float p = kk2 ? p1 : p0;
        const float* Ag = A  + (size_t)e * 2048;
        const float* Bg = Bm + (size_t)e * 2048;
        __syncthreads();    // prev GEMM2 done reading ATs/Bs (and Hs store visible)
#pragma unroll
        for (int i = 0; i < 2; i++) {
            int idx4 = tid + i * 256;           // 0..511 (2048 floats, 32x64)
            int row = idx4 >> 4, c4 = idx4 & 15;
            *(float4*)&ATs[row * 68 + c4 * 4] = *(const float4*)&Ag[idx4 * 4];
            *(float4*)&Bs[row * 68 + c4 * 4]  = *(const float4*)&Bg[idx4 * 4];
        }
        __syncthreads();

        // GEMM1: T = A @ H ; warp: mtile rows, n-tiles ntile2*2 + {0,1}
        float t1[2][4];
#pragma unroll
        for (int t = 0; t < 2; t++)
#pragma unroll
            for (int q = 0; q < 4; q++) t1[t][q] = 0.f;
#pragma unroll
        for (int kk = 0; kk < 8; kk++) {
            int k0 = kk * 8;
            int aoff = (mtile * 16 + grp) * 68 + k0 + qc;
            LDFRAG_A(ATs, 68, aoff);
#pragma unroll
            for (int t = 0; t < 2; t++) {
                // B-op = H col-major (k=i, n=j): addr (k0+qc)*72 + n0+grp
                int boff = (k0 + qc) * 72 + (ntile2 * 2 + t) * 8 + grp;
                uint32_t bh0, bh1, bl0, bl1;
                sp(Hs[boff],          bh0, bl0);
                sp(Hs[boff + 4 * 72], bh1, bl1);
                MMA3(t1[t], ah0, ah1, ah2, ah3, al0, al1, al2, al3, bh0, bh1, bl0, bl1);
            }
        }
        __syncthreads();    // all warps done reading As before Ts overwrites it
        {
            int row0 = mtile * 16 + grp;
#pragma unroll
            for (int t = 0; t < 2; t++) {
                int col0 = (ntile2 * 2 + t) * 8 + 2 * qc;
                *(float2*)&ATs[row0 * 68 + col0]       = make_float2(p * t1[t][0], p * t1[t][1]);
                *(float2*)&ATs[(row0 + 8) * 68 + col0] = make_float2(p * t1[t][2], p * t1[t][3]);
            }
        }
        __syncthreads();

        // GEMM2: Y += T @ B^T
#pragma unroll
        for (int kk = 0; kk < 8; kk++) {
            int k0 = kk * 8;
            int aoff = (mtile * 16 + grp) * 68 + k0 + qc;
            LDFRAG_A(ATs, 68, aoff);
            int boff = (ntile2 * 8 + grp) * 68 + k0 + qc;
            LDFRAG_B(Bs, boff);
            MMA3(c, ah0, ah1, ah2, ah3, al0, al1, al2, al3, bh0, bh1, bl0, bl1);
        }
    }

    float* orow = out + (size_t)n * 1024;
    const int row0 = mtile * 16 + grp;
    const int col0 = ntile2 * 8 + 2 * qc;
#pragma unroll
    for (int half = 0; half < 2; half++) {
        int row = row0 + half * 8;
        int oi = row * 32 + col0;
        float2 bv = *(const float2*)&bias[oi];
        float y0 = c[half * 2 + 0] * sc + bv.x;
        float y1 = c[half * 2 + 1] * sc + bv.y;
        *(float2*)(orow + oi) = make_float2(y0, y1);
    }
}

// ---------------------------------------------------------------------------
extern "C" void kernel_launch(void* const* d_in, const int* in_sizes, int n_in,
                              void* d_out, int out_size)
{
    const float* x        = (const float*)d_in[0];
    const float* W_up     = (const float*)d_in[1];
    const float* A_up     = (const float*)d_in[2];
    const float* B_up     = (const float*)d_in[3];
    const float* scale_up = (const float*)d_in[4];
    const float* bias_up  = (const float*)d_in[5];
    const float* W_dn     = (const float*)d_in[6];
    const float* A_dn     = (const float*)d_in[7];
    const float* B_dn     = (const float*)d_in[8];
    const float* scale_dn = (const float*)d_in[9];
    const float* bias_dn  = (const float*)d_in[10];
    float* out = (float*)d_out;

    const int N = in_sizes[0] / 1024;   // 8192 tokens

    // prefer max shared-memory carveout (occupancy is smem-limited)
    cudaFuncSetAttribute(router_mma, cudaFuncAttributePreferredSharedMemoryCarveout, 100);
    cudaFuncSetAttribute(up_mma,     cudaFuncAttributePreferredSharedMemoryCarveout, 100);
    cudaFuncSetAttribute(down_mma,   cudaFuncAttributePreferredSharedMemoryCarveout, 100);

    float* hptr = nullptr;
    cudaGetSymbolAddress((void**)&hptr, g_h);

    router_mma<<<N / 64, 256>>>(x, W_up, 1024, 0);
    up_mma<<<N, 256>>>(x, A_up, B_up, scale_up, bias_up);
    router_mma<<<N / 64, 256>>>(hptr, W_dn, 4096, 1);
    down_mma<<<N, 256>>>(A_dn, B_dn, scale_dn, bias_dn, out);
}

// round 10
// speedup vs baseline: 1.5864x; 1.0804x over previous
#include <cuda_runtime.h>
#include <math.h>
#include <stdint.h>

// Fixed shapes for this dataset
#define NTOK_MAX 8192

// Scratch (no cudaMalloc allowed)
__device__ float g_h[NTOK_MAX * 4096];        // 128 MB intermediate (post-GELU)
__device__ int   g_eidx_up[NTOK_MAX * 2];
__device__ float g_prob_up[NTOK_MAX * 2];
__device__ int   g_eidx_dn[NTOK_MAX * 2];
__device__ float g_prob_dn[NTOK_MAX * 2];

// fp16x3 split: v = h + l. h = v with low 13 mantissa bits cleared (LOP3) —
// exactly representable in fp16 (10-bit mantissa), so cvt.rn.f16x2 of h is
// exact and l = v - h is exact in fp32. 3 mma keep hh+hl+lh; dropped ll~2^-22.
// sp2 packs a k-adjacent pair (x=elem k -> lo half, y=elem k+1 -> hi half).
__device__ __forceinline__ void sp2(float x, float y, uint32_t& hp, uint32_t& lp) {
    float h0 = __uint_as_float(__float_as_uint(x) & 0xFFFFE000u);
    float h1 = __uint_as_float(__float_as_uint(y) & 0xFFFFE000u);
    float l0 = x - h0, l1 = y - h1;
    asm("cvt.rn.f16x2.f32 %0, %1, %2;" : "=r"(hp) : "f"(h1), "f"(h0));
    asm("cvt.rn.f16x2.f32 %0, %1, %2;" : "=r"(lp) : "f"(l1), "f"(l0));
}

#define MMA_F16(C, a0, a1, a2, a3, b0, b1)                                     \
    asm volatile(                                                              \
        "mma.sync.aligned.m16n8k16.row.col.f32.f16.f16.f32 "                   \
        "{%0,%1,%2,%3},{%4,%5,%6,%7},{%8,%9},{%0,%1,%2,%3};"                   \
        : "+f"((C)[0]), "+f"((C)[1]), "+f"((C)[2]), "+f"((C)[3])               \
        : "r"(a0), "r"(a1), "r"(a2), "r"(a3), "r"(b0), "r"(b1));

#define MMA3(C)                                                                \
    MMA_F16(C, ah0, ah1, ah2, ah3, bh0, bh1);                                  \
    MMA_F16(C, ah0, ah1, ah2, ah3, bl0, bl1);                                  \
    MMA_F16(C, al0, al1, al2, al3, bh0, bh1);

// A-fragment (m16 k16) from row-major tile, STRIDE ≡ 8 (mod 32): float2 loads
// conflict-free. aoff = (m0+grp)*STRIDE + k0 + 2*qc.
#define LDFRAG_A16(S, STRIDE, aoff)                                            \
    uint32_t ah0, ah1, ah2, ah3, al0, al1, al2, al3;                           \
    {                                                                          \
        float2 v;                                                              \
        v = *(const float2*)&(S)[(aoff)];                  sp2(v.x, v.y, ah0, al0); \
        v = *(const float2*)&(S)[(aoff) + 8 * (STRIDE)];   sp2(v.x, v.y, ah1, al1); \
        v = *(const float2*)&(S)[(aoff) + 8];              sp2(v.x, v.y, ah2, al2); \
        v = *(const float2*)&(S)[(aoff) + 8 * (STRIDE) + 8]; sp2(v.x, v.y, ah3, al3); \
    }

// B-fragment (n8 k16) from row-major k-major weight tile [n][k], STRIDE ≡ 8.
// boff = (n0+grp)*STRIDE + k0 + 2*qc.
#define LDFRAG_B16(S, STRIDE, boff)                                            \
    uint32_t bh0, bh1, bl0, bl1;                                               \
    {                                                                          \
        float2 v;                                                              \
        v = *(const float2*)&(S)[(boff)];       sp2(v.x, v.y, bh0, bl0);       \
        v = *(const float2*)&(S)[(boff) + 8];   sp2(v.x, v.y, bh1, bl1);       \
    }

// B-fragment from row-major activation tile [k][n] read col-major, STRIDE ≡ 4
// (mod 32): scalar reads at rows k0q..k0q+1, k0q+8..k0q+9, col n0g.
#define LDFRAG_BT16(S, STRIDE, n0g, k0q)                                       \
    uint32_t bh0, bh1, bl0, bl1;                                               \
    {                                                                          \
        float x0 = (S)[(k0q) * (STRIDE) + (n0g)];                              \
        float x1 = (S)[((k0q) + 1) * (STRIDE) + (n0g)];                        \
        sp2(x0, x1, bh0, bl0);                                                 \
        float x2 = (S)[((k0q) + 8) * (STRIDE) + (n0g)];                        \
        float x3 = (S)[((k0q) + 9) * (STRIDE) + (n0g)];                        \
        sp2(x2, x3, bh1, bl1);                                                 \
    }

// ---------------------------------------------------------------------------
// Router: logits = X[N,K] @ W[E,K]^T via fp16x3 mma, then top-2 + softmax(2).
// Block = 64 tokens x 64 experts. 256 threads = 8 warps. LDG double buffering.
// Xs/Ws stride 40 (≡8 mod 32) for conflict-free float2 fragment loads.
// ---------------------------------------------------------------------------
__global__ void __launch_bounds__(256) router_mma(const float* __restrict__ X,
                                                  const float* __restrict__ W,
                                                  int K, int phase)
{
    __shared__ float Xs[64 * 40];
    __shared__ float Ws[64 * 40];
    __shared__ float Ls[64 * 65];

    const int tid  = threadIdx.x;
    const int w    = tid >> 5;
    const int lane = tid & 31;
    const int grp  = lane >> 2;
    const int qc   = lane & 3;
    const int tok0 = blockIdx.x * 64;
    const int mtile = w >> 1;
    const int nbase = (w & 1) * 4;

    const int r0 = tid >> 3,            c0 = (tid & 7) * 4;
    const int r1 = (tid + 256) >> 3,    c1 = ((tid + 256) & 7) * 4;

    float c[4][4];
#pragma unroll
    for (int t = 0; t < 4; t++)
#pragma unroll
        for (int q = 0; q < 4; q++) c[t][q] = 0.f;

    const int nT = K >> 5;
    float4 xv0, xv1, wv0, wv1;
    xv0 = *(const float4*)&X[(size_t)(tok0 + r0) * K + c0];
    xv1 = *(const float4*)&X[(size_t)(tok0 + r1) * K + c1];
    wv0 = *(const float4*)&W[(size_t)r0 * K + c0];
    wv1 = *(const float4*)&W[(size_t)r1 * K + c1];

    for (int ti = 0; ti < nT; ti++) {
        *(float4*)&Xs[r0 * 40 + c0] = xv0;
        *(float4*)&Xs[r1 * 40 + c1] = xv1;
        *(float4*)&Ws[r0 * 40 + c0] = wv0;
        *(float4*)&Ws[r1 * 40 + c1] = wv1;
        __syncthreads();

        if (ti + 1 < nT) {
            int kt = (ti + 1) * 32;
            xv0 = *(const float4*)&X[(size_t)(tok0 + r0) * K + kt + c0];
            xv1 = *(const float4*)&X[(size_t)(tok0 + r1) * K + kt + c1];
            wv0 = *(const float4*)&W[(size_t)r0 * K + kt + c0];
            wv1 = *(const float4*)&W[(size_t)r1 * K + kt + c1];
        }

#pragma unroll
        for (int kk = 0; kk < 2; kk++) {
            int k0 = kk * 16;
            int aoff = (mtile * 16 + grp) * 40 + k0 + 2 * qc;
            LDFRAG_A16(Xs, 40, aoff);
#pragma unroll
            for (int t = 0; t < 4; t++) {
                int boff = ((nbase + t) * 8 + grp) * 40 + k0 + 2 * qc;
                LDFRAG_B16(Ws, 40, boff);
                MMA3(c[t]);
            }
        }
        __syncthreads();
    }

    {
        int row0 = mtile * 16 + grp;
#pragma unroll
        for (int t = 0; t < 4; t++) {
            int col0 = (nbase + t) * 8 + 2 * qc;
            Ls[row0 * 65 + col0]           = c[t][0];
            Ls[row0 * 65 + col0 + 1]       = c[t][1];
            Ls[(row0 + 8) * 65 + col0]     = c[t][2];
            Ls[(row0 + 8) * 65 + col0 + 1] = c[t][3];
        }
    }
    __syncthreads();

    if (tid < 64) {
        const float* lrow = &Ls[tid * 65];
        float v0 = -1e30f; int i0 = 0;
#pragma unroll
        for (int e = 0; e < 64; e++) {
            float v = lrow[e];
            if (v > v0) { v0 = v; i0 = e; }
        }
        float v1 = -1e30f; int i1 = 0;
#pragma unroll
        for (int e = 0; e < 64; e++) {
            if (e == i0) continue;
            float v = lrow[e];
            if (v > v1) { v1 = v; i1 = e; }
        }
        float p0 = 1.0f / (1.0f + expf(v1 - v0));
        float p1 = 1.0f - p0;
        int n = tok0 + tid;
        int*   ei = phase ? g_eidx_dn : g_eidx_up;
        float* pr = phase ? g_prob_dn : g_prob_up;
        ei[n * 2 + 0] = i0;
        ei[n * 2 + 1] = i1;
        pr[n * 2 + 0] = p0;
        pr[n * 2 + 1] = p1;
    }
}

// ---------------------------------------------------------------------------
// Up layer (per token): Y = sum_k p_k * (A_e @ X @ B_e^T), X as 32x32 [i][j].
// Xs stride 36 (≡4: conflict-free col-major scalar reads).
// ATs/Bs stride 40 (≡8: conflict-free float2 fragment loads). ATs aliases
// As (GEMM1 A-op) and Ts (GEMM2 A-op); lifetimes separated by a sync.
// ---------------------------------------------------------------------------
__global__ void __launch_bounds__(256) up_mma(const float* __restrict__ X,
                                              const float* __restrict__ A,
                                              const float* __restrict__ Bm,
                                              const float* __restrict__ scale,
                                              const float* __restrict__ bias)
{
    __shared__ float Xs[32 * 36];    // [i][j] row-major
    __shared__ float ATs[64 * 40];   // As (GEMM1) then Ts (GEMM2)
    __shared__ float Bs[64 * 40];    // B[p][j] k-major

    const int tid  = threadIdx.x;
    const int w    = tid >> 5;
    const int lane = tid & 31;
    const int grp  = lane >> 2;
    const int qc   = lane & 3;
    const int n    = blockIdx.x;
    const int mtile = w >> 1;
    const int nbase = (w & 1) * 4;

    {
        int i = tid >> 3, j4 = tid & 7;
        *(float4*)&Xs[i * 36 + j4 * 4] =
            *(const float4*)&X[(size_t)n * 1024 + i * 32 + j4 * 4];
    }

    const float sc = scale[0];
    const int   e0 = g_eidx_up[n * 2],  e1 = g_eidx_up[n * 2 + 1];
    const float p0 = g_prob_up[n * 2],  p1 = g_prob_up[n * 2 + 1];

    float c[4][4];
#pragma unroll
    for (int t = 0; t < 4; t++)
#pragma unroll
        for (int q = 0; q < 4; q++) c[t][q] = 0.f;

#pragma unroll 1
    for (int kk2 = 0; kk2 < 2; kk2++) {
        const int   e = kk2 ? e1 : e0;
        const float p = kk2 ? p1 : p0;
        const float* Ag = A  + (size_t)e * 2048;
        const float* Bg = Bm + (size_t)e * 2048;
        __syncthreads();    // prev GEMM2 done reading ATs/Bs (and Xs store visible)
#pragma unroll
        for (int i = 0; i < 2; i++) {
            int idx4 = tid + i * 256;           // 0..511 (2048 floats, 64x32)
            int row = idx4 >> 3, c4 = idx4 & 7;
            *(float4*)&ATs[row * 40 + c4 * 4] = *(const float4*)&Ag[idx4 * 4];
            *(float4*)&Bs[row * 40 + c4 * 4]  = *(const float4*)&Bg[idx4 * 4];
        }
        __syncthreads();

        // GEMM1: T = A @ X  (K=32 -> 2 k16 steps); n-tiles (w&1)*2 + {0,1}
        float t1[2][4];
#pragma unroll
        for (int t = 0; t < 2; t++)
#pragma unroll
            for (int q = 0; q < 4; q++) t1[t][q] = 0.f;
#pragma unroll
        for (int kk = 0; kk < 2; kk++) {
            int k0 = kk * 16;
            int aoff = (mtile * 16 + grp) * 40 + k0 + 2 * qc;
            LDFRAG_A16(ATs, 40, aoff);
#pragma unroll
            for (int t = 0; t < 2; t++) {
                int n0g = ((w & 1) * 2 + t) * 8 + grp;
                LDFRAG_BT16(Xs, 36, n0g, k0 + 2 * qc);
                MMA3(t1[t]);
            }
        }
        __syncthreads();    // all warps done reading As before Ts overwrites it
        {
            int row0 = mtile * 16 + grp;
#pragma unroll
            for (int t = 0; t < 2; t++) {
                int col0 = ((w & 1) * 2 + t) * 8 + 2 * qc;
                *(float2*)&ATs[row0 * 40 + col0]       = make_float2(p * t1[t][0], p * t1[t][1]);
                *(float2*)&ATs[(row0 + 8) * 40 + col0] = make_float2(p * t1[t][2], p * t1[t][3]);
            }
        }
        __syncthreads();

        // GEMM2: Y += T @ B^T  (K=32 -> 2 k16 steps)
#pragma unroll
        for (int kk = 0; kk < 2; kk++) {
            int k0 = kk * 16;
            int aoff = (mtile * 16 + grp) * 40 + k0 + 2 * qc;
            LDFRAG_A16(ATs, 40, aoff);
#pragma unroll
            for (int t = 0; t < 4; t++) {
                int boff = ((nbase + t) * 8 + grp) * 40 + k0 + 2 * qc;
                LDFRAG_B16(Bs, 40, boff);
                MMA3(c[t]);
            }
        }
    }

    // epilogue: scale + bias + exact erf GELU
    float* Hrow = g_h + (size_t)n * 4096;
    const int row0 = mtile * 16 + grp;
#pragma unroll
    for (int t = 0; t < 4; t++) {
        int col0 = (nbase + t) * 8 + 2 * qc;
#pragma unroll
        for (int half = 0; half < 2; half++) {
            int row = row0 + half * 8;
            int oi = row * 64 + col0;
            float2 bv = *(const float2*)&bias[oi];
            float y0 = c[t][half * 2 + 0] * sc + bv.x;
            float y1 = c[t][half * 2 + 1] * sc + bv.y;
            float g0 = 0.5f * y0 * (1.0f + erff(y0 * 0.70710678118654752f));
            float g1 = 0.5f * y1 * (1.0f + erff(y1 * 0.70710678118654752f));
            *(float2*)(Hrow + oi) = make_float2(g0, g1);
        }
    }
}

// ---------------------------------------------------------------------------
// Down layer (per token): Y = sum_k p_k * (A_e @ H @ B_e^T), H as 64x64 [i][j].
// Hs stride 68 (≡4: conflict-free col-major reads).
// ATs/Bs stride 72 (≡8: conflict-free float2 fragment loads); ATs aliased.
// ---------------------------------------------------------------------------
__global__ void __launch_bounds__(256) down_mma(const float* __restrict__ A,
                                                const float* __restrict__ Bm,
                                                const float* __restrict__ scale,
                                                const float* __restrict__ bias,
                                                float* __restrict__ out)
{
    __shared__ float Hs[64 * 68];    // [i][j] row-major
    __shared__ float ATs[32 * 72];   // As (GEMM1) then Ts (GEMM2)
    __shared__ float Bs[32 * 72];    // B[p][j] k-major

    const int tid  = threadIdx.x;
    const int w    = tid >> 5;
    const int lane = tid & 31;
    const int grp  = lane >> 2;
    const int qc   = lane & 3;
    const int n    = blockIdx.x;
    const int mtile  = w & 1;
    const int ntile2 = w >> 1;

    const float* Xrow = g_h + (size_t)n * 4096;
#pragma unroll
    for (int i = 0; i < 4; i++) {
        int idx4 = tid + i * 256;               // 0..1023
        int r = idx4 >> 4, j4 = idx4 & 15;
        *(float4*)&Hs[r * 68 + j4 * 4] = *(const float4*)&Xrow[idx4 * 4];
    }

    const float sc = scale[0];
    const int   e0 = g_eidx_dn[n * 2],  e1 = g_eidx_dn[n * 2 + 1];
    const float p0 = g_prob_dn[n * 2],  p1 = g_prob_dn[n * 2 + 1];

    float c[4];
    c[0] = c[1] = c[2] = c[3] = 0.f;

#pragma unroll 1
    for (int kk2 = 0; kk2 < 2; kk2++) {
        const int   e = kk2 ? e1 : e0;
        const float p = kk2 ? p1 : p0;
        const float* Ag = A  + (size_t)e * 2048;
        const float* Bg = Bm + (size_t)e * 2048;
        __syncthreads();    // prev GEMM2 done reading ATs/Bs (and Hs store visible)
#pragma unroll
        for (int i = 0; i < 2; i++) {
            int idx4 = tid + i * 256;           // 0..511 (2048 floats, 32x64)
            int row = idx4 >> 4, c4 = idx4 & 15;
            *(float4*)&ATs[row * 72 + c4 * 4] = *(const float4*)&Ag[idx4 * 4];
            *(float4*)&Bs[row * 72 + c4 * 4]  = *(const float4*)&Bg[idx4 * 4];
        }
        __syncthreads();

        // GEMM1: T = A @ H  (K=64 -> 4 k16 steps); n-tiles ntile2*2 + {0,1}
        float t1[2][4];
#pragma unroll
        for (int t = 0; t < 2; t++)
#pragma unroll
            for (int q = 0; q < 4; q++) t1[t][q] = 0.f;
#pragma unroll
        for (int kk = 0; kk < 4; kk++) {
            int k0 = kk * 16;
            int aoff = (mtile * 16 + grp) * 72 + k0 + 2 * qc;
            LDFRAG_A16(ATs, 72, aoff);
#pragma unroll
            for (int t = 0; t < 2; t++) {
                int n0g = (ntile2 * 2 + t) * 8 + grp;
                LDFRAG_BT16(Hs, 68, n0g, k0 + 2 * qc);
                MMA3(t1[t]);
            }
        }
        __syncthreads();    // all warps done reading As before Ts overwrites it
        {
            int row0 = mtile * 16 + grp;
#pragma unroll
            for (int t = 0; t < 2; t++) {
                int col0 = (ntile2 * 2 + t) * 8 + 2 * qc;
                *(float2*)&ATs[row0 * 72 + col0]       = make_float2(p * t1[t][0], p * t1[t][1]);
                *(float2*)&ATs[(row0 + 8) * 72 + col0] = make_float2(p * t1[t][2], p * t1[t][3]);
            }
        }
        __syncthreads();

        // GEMM2: Y += T @ B^T  (K=64 -> 4 k16 steps)
#pragma unroll
        for (int kk = 0; kk < 4; kk++) {
            int k0 = kk * 16;
            int aoff = (mtile * 16 + grp) * 72 + k0 + 2 * qc;
            LDFRAG_A16(ATs, 72, aoff);
            int boff = (ntile2 * 8 + grp) * 72 + k0 + 2 * qc;
            LDFRAG_B16(Bs, 72, boff);
            MMA3(c);
        }
    }

    float* orow = out + (size_t)n * 1024;
    const int row0 = mtile * 16 + grp;
    const int col0 = ntile2 * 8 + 2 * qc;
#pragma unroll
    for (int half = 0; half < 2; half++) {
        int row = row0 + half * 8;
        int oi = row * 32 + col0;
        float2 bv = *(const float2*)&bias[oi];
        float y0 = c[half * 2 + 0] * sc + bv.x;
        float y1 = c[half * 2 + 1] * sc + bv.y;
        *(float2*)(orow + oi) = make_float2(y0, y1);
    }
}

// ---------------------------------------------------------------------------
extern "C" void kernel_launch(void* const* d_in, const int* in_sizes, int n_in,
                              void* d_out, int out_size)
{
    const float* x        = (const float*)d_in[0];
    const float* W_up     = (const float*)d_in[1];
    const float* A_up     = (const float*)d_in[2];
    const float* B_up     = (const float*)d_in[3];
    const float* scale_up = (const float*)d_in[4];
    const float* bias_up  = (const float*)d_in[5];
    const float* W_dn     = (const float*)d_in[6];
    const float* A_dn     = (const float*)d_in[7];
    const float* B_dn     = (const float*)d_in[8];
    const float* scale_dn = (const float*)d_in[9];
    const float* bias_dn  = (const float*)d_in[10];
    float* out = (float*)d_out;

    const int N = in_sizes[0] / 1024;   // 8192 tokens

    float* hptr = nullptr;
    cudaGetSymbolAddress((void**)&hptr, g_h);

    router_mma<<<N / 64, 256>>>(x, W_up, 1024, 0);
    up_mma<<<N, 256>>>(x, A_up, B_up, scale_up, bias_up);
    router_mma<<<N / 64, 256>>>(hptr, W_dn, 4096, 1);
    down_mma<<<N, 256>>>(A_dn, B_dn, scale_dn, bias_dn, out);
}